// round 15
// baseline (speedup 1.0000x reference)
#include <cuda_runtime.h>
#include <math.h>
#include <stdint.h>
#include <stddef.h>

// ---------------- problem dims ----------------
#define B_    64
#define N_    4096
#define DIN_  256
#define K_    8
#define D_    256
#define H_    512
#define BK_   512
#define SCALE_ 0.0625f
#define EPSLN 1e-5f
#define EPSA  1e-8f

typedef unsigned long long u64;

// ---------------- device scratch ----------------
__device__ __align__(16) float g_slots[BK_ * D_];
__device__ __align__(16) float g_gq[BK_ * D_];
__device__ float g_C1[BK_];
__device__ float g_C2[BK_];
__device__ __align__(16) float g_P[BK_ * D_];
__device__ float g_SA[BK_];
__device__ float g_SW[BK_];
__device__ float g_bqk[D_];
__device__ float g_wb[D_];
__device__ float g_c0;
// packed weights: Wp[(kb * Nout + o)*4 + t] = W[o][4*kb + t]
__device__ __align__(16) float g_WqkP[D_ * D_];
__device__ __align__(16) float g_WihP[3 * D_ * D_];
__device__ __align__(16) float g_WhhP[3 * D_ * D_];
__device__ __align__(16) float g_WvP[D_ * D_];
__device__ __align__(16) float g_W1P[H_ * D_];
__device__ __align__(16) float g_W2P[D_ * H_];

// ---------------- f32x2 packed helpers ----------------
__device__ __forceinline__ u64 pk2(float x, float y) {
    u64 r; asm("mov.b64 %0, {%1, %2};" : "=l"(r) : "f"(x), "f"(y)); return r;
}
__device__ __forceinline__ void upk2(u64 v, float& x, float& y) {
    asm("mov.b64 {%0, %1}, %2;" : "=f"(x), "=f"(y) : "l"(v));
}
__device__ __forceinline__ void fma2(u64& d, u64 a, u64 b) {
    asm("fma.rn.f32x2 %0, %1, %2, %0;" : "+l"(d) : "l"(a), "l"(b));
}
__device__ __forceinline__ u64 add2(u64 a, u64 b) {
    u64 r; asm("add.rn.f32x2 %0, %1, %2;" : "=l"(r) : "l"(a), "l"(b)); return r;
}
__device__ __forceinline__ u64 mul2(u64 a, u64 b) {
    u64 r; asm("mul.rn.f32x2 %0, %1, %2;" : "=l"(r) : "l"(a), "l"(b)); return r;
}

// ---------------- cp.async helpers ----------------
__device__ __forceinline__ void cpasync16(uint32_t saddr, const void* gptr) {
    asm volatile("cp.async.cg.shared.global [%0], [%1], 16;" :: "r"(saddr), "l"(gptr) : "memory");
}
#define CP_COMMIT() asm volatile("cp.async.commit_group;" ::: "memory")
#define CP_WAIT1()  asm volatile("cp.async.wait_group 1;" ::: "memory")
#define CP_WAIT0()  asm volatile("cp.async.wait_group 0;" ::: "memory")

// ---------------- block reduce (256-thread kernels) ----------------
__device__ __forceinline__ void blockReduce2(float& a, float& b) {
    #pragma unroll
    for (int o = 16; o; o >>= 1) {
        a += __shfl_xor_sync(0xffffffffu, a, o);
        b += __shfl_xor_sync(0xffffffffu, b, o);
    }
    __shared__ float sa[8], sb[8];
    __syncthreads();
    int w = threadIdx.x >> 5;
    if ((threadIdx.x & 31) == 0) { sa[w] = a; sb[w] = b; }
    __syncthreads();
    a = sa[threadIdx.x & 7];
    b = sb[threadIdx.x & 7];
    #pragma unroll
    for (int o = 4; o; o >>= 1) {
        a += __shfl_xor_sync(0xffffffffu, a, o);
        b += __shfl_xor_sync(0xffffffffu, b, o);
    }
}

// ---------------- group reduce: 1024 threads, 4 groups of 256 ----------------
__device__ __forceinline__ void grpReduce2(float& a, float& b) {
    #pragma unroll
    for (int o = 16; o; o >>= 1) {
        a += __shfl_xor_sync(0xffffffffu, a, o);
        b += __shfl_xor_sync(0xffffffffu, b, o);
    }
    __shared__ float sa[32], sb[32];
    int w = threadIdx.x >> 5;
    __syncthreads();
    if ((threadIdx.x & 31) == 0) { sa[w] = a; sb[w] = b; }
    __syncthreads();
    int g8 = (threadIdx.x >> 8) << 3;
    float ra = 0.f, rb = 0.f;
    #pragma unroll
    for (int i = 0; i < 8; i++) { ra += sa[g8 + i]; rb += sb[g8 + i]; }
    a = ra; b = rb;
}

// ---------------- packed GEMV, 8 rows ----------------
__device__ __forceinline__ void gemvPQ8(const float* __restrict__ Wp, int Nout, int nblk, int kb0,
                                        const float* s_in, int in_stride, int j, float acc[8]) {
    const float4* p = (const float4*)Wp + (size_t)kb0 * Nout + j;
    #pragma unroll 4
    for (int b = 0; b < nblk; b++) {
        float4 w = p[(size_t)b * Nout];
        #pragma unroll
        for (int r = 0; r < 8; r++) {
            float4 x = *(const float4*)(s_in + r * in_stride + (kb0 + b) * 4);
            acc[r] = fmaf(x.x, w.x, fmaf(x.y, w.y, fmaf(x.z, w.z, fmaf(x.w, w.w, acc[r]))));
        }
    }
}

// ---------------- reduction wave, 8 rows: thread (q,j) gets rows 2q, 2q+1 ----------------
__device__ __forceinline__ void reduceWave8(const float part[8], float* sRed, int q, int j,
                                            float& vA, float& vB) {
    __syncthreads();
    #pragma unroll
    for (int r = 0; r < 8; r++) sRed[(q * 8 + r) * 256 + j] = part[r];
    __syncthreads();
    int rA = 2 * q, rB = 2 * q + 1;
    vA = (sRed[rA * 256 + j] + sRed[(8 + rA) * 256 + j]) +
         (sRed[(16 + rA) * 256 + j] + sRed[(24 + rA) * 256 + j]);
    vB = (sRed[rB * 256 + j] + sRed[(8 + rB) * 256 + j]) +
         (sRed[(16 + rB) * 256 + j] + sRed[(24 + rB) * 256 + j]);
}

// ---------------- slot-A body, 8 rows/block ----------------
__device__ __forceinline__ void slotABody8(const float (*s_sn)[256], float* sRed,
                                           int r0, int q, int j,
                                           const float* __restrict__ gg, const float* __restrict__ gb) {
    float acc[8] = {};
    gemvPQ8(g_WqkP, 256, 16, 16 * q, &s_sn[0][0], 256, j, acc);
    float qtA, qtB;
    reduceWave8(acc, sRed, q, j, qtA, qtB);
    float bqk = g_bqk[j], ggj = gg[j], gbj = gb[j], wbj = g_wb[j], c0 = g_c0;
    int rA = r0 + 2 * q, rB = rA + 1;
    qtA += bqk; qtB += bqk;
    float gqA = ggj * qtA, gqB = ggj * qtB;
    g_gq[(size_t)rA * 256 + j] = gqA;
    g_gq[(size_t)rB * 256 + j] = gqB;
    {
        float c1 = gqA;
        float c2 = fmaf(qtA, gbj, s_sn[2 * q][j] * wbj);
        grpReduce2(c1, c2);
        if (j == 0) { g_C1[rA] = c1; g_C2[rA] = c2 + c0; }
    }
    {
        float c1 = gqB;
        float c2 = fmaf(qtB, gbj, s_sn[2 * q + 1][j] * wbj);
        grpReduce2(c1, c2);
        if (j == 0) { g_C1[rB] = c1; g_C2[rB] = c2 + c0; }
    }
    g_P[(size_t)rA * 256 + j] = 0.f;
    g_P[(size_t)rB * 256 + j] = 0.f;
    if (j == 0) { g_SA[rA] = 0.f; g_SW[rA] = 0.f; g_SA[rB] = 0.f; g_SW[rB] = 0.f; }
}

// =================== SETUP ===================
__device__ __forceinline__ void packTile(const float* __restrict__ src, float* __restrict__ dst,
                                         int Nout, int Kb, int blk) {
    int e = blk * 256 + threadIdx.x;
    int o = e / Kb, kb = e - o * Kb;
    float4 v = *(const float4*)(src + (size_t)o * Kb * 4 + (size_t)kb * 4);
    *(float4*)(dst + ((size_t)kb * Nout + o) * 4) = v;
}

__global__ void __launch_bounds__(256) kSetup(const float* __restrict__ W_ih, const float* __restrict__ W_hh,
                                              const float* __restrict__ Wv, const float* __restrict__ W1,
                                              const float* __restrict__ W2, const float* __restrict__ noise,
                                              const float* __restrict__ mu, const float* __restrict__ ls,
                                              const float* __restrict__ Wq, const float* __restrict__ Wk,
                                              const float* __restrict__ bq, const float* __restrict__ bk) {
    int t = blockIdx.x;
    int i = threadIdx.x;
    if (t < 192)       packTile(W_ih, g_WihP, 768, 64, t);
    else if (t < 384)  packTile(W_hh, g_WhhP, 768, 64, t - 192);
    else if (t < 448)  packTile(Wv,   g_WvP,  256, 64, t - 384);
    else if (t < 576)  packTile(W1,   g_W1P,  512, 64, t - 448);
    else if (t < 704)  packTile(W2,   g_W2P,  256, 128, t - 576);
    else if (t < 1216) {
        int idx = (t - 704) * 256 + i;
        int d = idx & 255;
        g_slots[idx] = mu[d] + __expf(ls[d]) * noise[idx];
    } else if (t < 1472) {
        int jj = t - 1216;
        float acc[8] = {0.f,0.f,0.f,0.f,0.f,0.f,0.f,0.f};
        #pragma unroll 4
        for (int d = 0; d < 256; d += 8) {
            #pragma unroll
            for (int u = 0; u < 8; u++)
                acc[u] = fmaf(Wq[(d + u) * 256 + jj], Wk[(d + u) * 256 + i], acc[u]);
        }
        float v = (((acc[0] + acc[1]) + (acc[2] + acc[3])) + ((acc[4] + acc[5]) + (acc[6] + acc[7]))) * SCALE_;
        g_WqkP[(((size_t)(jj >> 2)) * 256 + i) * 4 + (jj & 3)] = v;
    } else if (t == 1472) {
        float a = 0.f;
        #pragma unroll 8
        for (int d = 0; d < 256; d++) a = fmaf(bq[d], Wk[d * 256 + i], a);
        g_bqk[i] = a * SCALE_;
    } else if (t == 1473) {
        float a = 0.f;
        #pragma unroll 8
        for (int d = 0; d < 256; d++) a = fmaf(Wq[d * 256 + i], bk[d], a);
        g_wb[i] = a * SCALE_;
    } else {
        float a = bq[i] * bk[i], dm = 0.f;
        blockReduce2(a, dm);
        if (i == 0) g_c0 = a * SCALE_;
    }
}

// =================== kSlotA (iteration 0 only): 64 blocks x 8 rows ===================
__global__ void __launch_bounds__(1024) kSlotA(const float* __restrict__ ls_g, const float* __restrict__ ls_b,
                                               const float* __restrict__ gg, const float* __restrict__ gb) {
    __shared__ float sSN[8][256];
    __shared__ float sRed[8192];
    int j = threadIdx.x & 255, q = threadIdx.x >> 8;
    int r0 = blockIdx.x * 8;
    float lsg = ls_g[j], lsb = ls_b[j];
    #pragma unroll
    for (int h = 0; h < 2; h++) {
        int rr = 2 * q + h;
        float v = g_slots[(size_t)(r0 + rr) * 256 + j];
        float a = v, b = v * v;
        grpReduce2(a, b);
        float m = a * (1.0f / 256.0f);
        float var = b * (1.0f / 256.0f) - m * m;
        float rs = rsqrtf(var + EPSLN);
        sSN[rr][j] = (v - m) * rs * lsg + lsb;
    }
    __syncthreads();
    slotABody8(sSN, sRed, r0, q, j, gg, gb);
}

// ============ kFA: cp.async-pipelined 2-row interleaved attention pass (unchanged R14) ============
__global__ void __launch_bounds__(128, 4) kFA(const float* __restrict__ inputs,
                                              int last, float* __restrict__ out_attn) {
    int b = blockIdx.y;
    int warp = threadIdx.x >> 5, lane = threadIdx.x & 31;
    int row0 = blockIdx.x * 512 + warp * 128;
    int r8 = b * 8;
    int slane = ((lane & 1) << 2) | (lane & 2) | ((lane >> 2) & 1);

    __shared__ __align__(16) float sGQ[8][256];
    __shared__ __align__(16) float sBuf[8192];
    __shared__ float sSA[4][8], sSW[4][8];

    {
        const float4* src = (const float4*)(g_gq + (size_t)r8 * 256);
        #pragma unroll
        for (int e = threadIdx.x; e < 512; e += 128)
            ((float4*)sGQ)[e] = src[e];
    }
    float C1s = g_C1[r8 + slane], C2s = g_C2[r8 + slane];
    __syncthreads();

    float* ring = sBuf + warp * 1536;
    uint32_t ringAddr = (uint32_t)__cvta_generic_to_shared(ring);
    const float* gbase = inputs + ((size_t)b * N_ + row0) * 256;

    u64 P[8][4];
    #pragma unroll
    for (int k = 0; k < 8; k++) { P[k][0] = 0; P[k][1] = 0; P[k][2] = 0; P[k][3] = 0; }
    float SAl = 0.f, SWl = 0.f;

    #pragma unroll
    for (int pr = 0; pr < 2; pr++) {
        const float* gsrc = gbase + (size_t)pr * 512;
        uint32_t sdst = ringAddr + pr * 2048;
        #pragma unroll
        for (int c = 0; c < 4; c++)
            cpasync16(sdst + (c * 32 + lane) * 16, gsrc + (c * 32 + lane) * 4);
        CP_COMMIT();
    }

    #pragma unroll 1
    for (int p = 0; p < 64; p++) {
        CP_WAIT1();
        __syncwarp();
        const float* xb = ring + (p % 3) * 512;
        ulonglong2 X0 = *(const ulonglong2*)(xb + 4 * lane);
        ulonglong2 X1 = *(const ulonglong2*)(xb + 128 + 4 * lane);
        ulonglong2 Y0 = *(const ulonglong2*)(xb + 256 + 4 * lane);
        ulonglong2 Y1 = *(const ulonglong2*)(xb + 256 + 128 + 4 * lane);

        if (p < 62) {
            const float* gsrc = gbase + (size_t)(p + 2) * 512;
            uint32_t sdst = ringAddr + ((p + 2) % 3) * 2048;
            #pragma unroll
            for (int c = 0; c < 4; c++)
                cpasync16(sdst + (c * 32 + lane) * 16, gsrc + (c * 32 + lane) * 4);
        }
        CP_COMMIT();

        float sX, ssX, sY, ssY;
        {
            u64 s2  = add2(add2(X0.x, X0.y), add2(X1.x, X1.y));
            u64 ss2 = mul2(X0.x, X0.x);
            fma2(ss2, X0.y, X0.y); fma2(ss2, X1.x, X1.x); fma2(ss2, X1.y, X1.y);
            float lo, hi;
            upk2(s2, lo, hi);  sX  = lo + hi;
            upk2(ss2, lo, hi); ssX = lo + hi;
        }
        {
            u64 s2  = add2(add2(Y0.x, Y0.y), add2(Y1.x, Y1.y));
            u64 ss2 = mul2(Y0.x, Y0.x);
            fma2(ss2, Y0.y, Y0.y); fma2(ss2, Y1.x, Y1.x); fma2(ss2, Y1.y, Y1.y);
            float lo, hi;
            upk2(s2, lo, hi);  sY  = lo + hi;
            upk2(ss2, lo, hi); ssY = lo + hi;
        }
        bool odd = lane & 1;
        {
            float sendX = odd ? sX : ssX;
            float sendY = odd ? sY : ssY;
            float rcvX = __shfl_xor_sync(0xffffffffu, sendX, 1);
            float rcvY = __shfl_xor_sync(0xffffffffu, sendY, 1);
            float vX = odd ? (ssX + rcvX) : (sX + rcvX);
            float vY = odd ? (ssY + rcvY) : (sY + rcvY);
            vX += __shfl_xor_sync(0xffffffffu, vX, 2);
            vY += __shfl_xor_sync(0xffffffffu, vY, 2);
            vX += __shfl_xor_sync(0xffffffffu, vX, 4);
            vY += __shfl_xor_sync(0xffffffffu, vY, 4);
            vX += __shfl_xor_sync(0xffffffffu, vX, 8);
            vY += __shfl_xor_sync(0xffffffffu, vY, 8);
            vX += __shfl_xor_sync(0xffffffffu, vX, 16);
            vY += __shfl_xor_sync(0xffffffffu, vY, 16);
            float oX = __shfl_xor_sync(0xffffffffu, vX, 1);
            float oY = __shfl_xor_sync(0xffffffffu, vY, 1);
            sX  = odd ? oX : vX;  ssX = odd ? vX : oX;
            sY  = odd ? oY : vY;  ssY = odd ? vY : oY;
        }
        float mX   = sX * (1.0f / 256.0f);
        float mY   = sY * (1.0f / 256.0f);
        float rsX  = rsqrtf(fmaf(ssX, 1.0f / 256.0f, -mX * mX) + EPSLN);
        float rsY  = rsqrtf(fmaf(ssY, 1.0f / 256.0f, -mY * mY) + EPSLN);
        float wX   = mX * rsX;
        float wY   = mY * rsY;

        float dtX[8], dtY[8];
        #pragma unroll
        for (int k = 0; k < 8; k++) {
            ulonglong2 qa = *(const ulonglong2*)(&sGQ[k][4 * lane]);
            ulonglong2 qb = *(const ulonglong2*)(&sGQ[k][128 + 4 * lane]);
            u64 dX = mul2(X0.x, qa.x);
            u64 dY = mul2(Y0.x, qa.x);
            fma2(dX, X0.y, qa.y); fma2(dY, Y0.y, qa.y);
            fma2(dX, X1.x, qb.x); fma2(dY, Y1.x, qb.x);
            fma2(dX, X1.y, qb.y); fma2(dY, Y1.y, qb.y);
            float lo, hi;
            upk2(dX, lo, hi); dtX[k] = lo + hi;
            upk2(dY, lo, hi); dtY[k] = lo + hi;
        }
        float vdX, vdY;
        {
            bool c0 = lane & 1;
            float x0 = c0 ? dtX[0] : dtX[4], y0 = c0 ? dtY[0] : dtY[4];
            float x1 = c0 ? dtX[1] : dtX[5], y1 = c0 ? dtY[1] : dtY[5];
            float x2 = c0 ? dtX[2] : dtX[6], y2 = c0 ? dtY[2] : dtY[6];
            float x3 = c0 ? dtX[3] : dtX[7], y3 = c0 ? dtY[3] : dtY[7];
            x0 = __shfl_xor_sync(0xffffffffu, x0, 1); y0 = __shfl_xor_sync(0xffffffffu, y0, 1);
            x1 = __shfl_xor_sync(0xffffffffu, x1, 1); y1 = __shfl_xor_sync(0xffffffffu, y1, 1);
            x2 = __shfl_xor_sync(0xffffffffu, x2, 1); y2 = __shfl_xor_sync(0xffffffffu, y2, 1);
            x3 = __shfl_xor_sync(0xffffffffu, x3, 1); y3 = __shfl_xor_sync(0xffffffffu, y3, 1);
            float uX0 = (c0 ? dtX[4] : dtX[0]) + x0, uY0 = (c0 ? dtY[4] : dtY[0]) + y0;
            float uX1 = (c0 ? dtX[5] : dtX[1]) + x1, uY1 = (c0 ? dtY[5] : dtY[1]) + y1;
            float uX2 = (c0 ? dtX[6] : dtX[2]) + x2, uY2 = (c0 ? dtY[6] : dtY[2]) + y2;
            float uX3 = (c0 ? dtX[7] : dtX[3]) + x3, uY3 = (c0 ? dtY[7] : dtY[3]) + y3;
            bool c1 = lane & 2;
            float aX0 = c1 ? uX0 : uX2, aY0 = c1 ? uY0 : uY2;
            float aX1 = c1 ? uX1 : uX3, aY1 = c1 ? uY1 : uY3;
            aX0 = __shfl_xor_sync(0xffffffffu, aX0, 2); aY0 = __shfl_xor_sync(0xffffffffu, aY0, 2);
            aX1 = __shfl_xor_sync(0xffffffffu, aX1, 2); aY1 = __shfl_xor_sync(0xffffffffu, aY1, 2);
            float wX0 = (c1 ? uX2 : uX0) + aX0, wY0 = (c1 ? uY2 : uY0) + aY0;
            float wX1 = (c1 ? uX3 : uX1) + aX1, wY1 = (c1 ? uY3 : uY1) + aY1;
            bool c2 = lane & 4;
            float bX = c2 ? wX0 : wX1, bY = c2 ? wY0 : wY1;
            bX = __shfl_xor_sync(0xffffffffu, bX, 4); bY = __shfl_xor_sync(0xffffffffu, bY, 4);
            vdX = (c2 ? wX1 : wX0) + bX;
            vdY = (c2 ? wY1 : wY0) + bY;
            vdX += __shfl_xor_sync(0xffffffffu, vdX, 8);
            vdY += __shfl_xor_sync(0xffffffffu, vdY, 8);
            vdX += __shfl_xor_sync(0xffffffffu, vdX, 16);
            vdY += __shfl_xor_sync(0xffffffffu, vdY, 16);
        }
        float lgX = fmaf(rsX, vdX, fmaf(-wX, C1s, C2s));
        float lgY = fmaf(rsY, vdY, fmaf(-wY, C1s, C2s));
        float mxX = lgX, mxY = lgY;
        mxX = fmaxf(mxX, __shfl_xor_sync(0xffffffffu, mxX, 1));
        mxY = fmaxf(mxY, __shfl_xor_sync(0xffffffffu, mxY, 1));
        mxX = fmaxf(mxX, __shfl_xor_sync(0xffffffffu, mxX, 2));
        mxY = fmaxf(mxY, __shfl_xor_sync(0xffffffffu, mxY, 2));
        mxX = fmaxf(mxX, __shfl_xor_sync(0xffffffffu, mxX, 4));
        mxY = fmaxf(mxY, __shfl_xor_sync(0xffffffffu, mxY, 4));
        float eX = __expf(lgX - mxX);
        float eY = __expf(lgY - mxY);
        float smXv = eX, smYv = eY;
        smXv += __shfl_xor_sync(0xffffffffu, smXv, 1);
        smYv += __shfl_xor_sync(0xffffffffu, smYv, 1);
        smXv += __shfl_xor_sync(0xffffffffu, smXv, 2);
        smYv += __shfl_xor_sync(0xffffffffu, smYv, 2);
        smXv += __shfl_xor_sync(0xffffffffu, smXv, 4);
        smYv += __shfl_xor_sync(0xffffffffu, smYv, 4);
        float aX = __fdividef(eX, smXv);
        float aY = __fdividef(eY, smYv);
        SAl += aX + aY;
        SWl = fmaf(aX, wX, fmaf(aY, wY, SWl));
        if (last && lane < 8) {
            size_t base = (size_t)(r8 + slane) * N_ + row0 + 2 * p;
            out_attn[base] = aX;
            out_attn[base + 1] = aY;
        }

        float arX = aX * rsX;
        float arY = aY * rsY;
        int gbase2 = lane & 24;
        {
            float ak[8];
            ak[0] = __shfl_sync(0xffffffffu, arX, gbase2 | 0);
            ak[1] = __shfl_sync(0xffffffffu, arX, gbase2 | 4);
            ak[2] = __shfl_sync(0xffffffffu, arX, gbase2 | 2);
            ak[3] = __shfl_sync(0xffffffffu, arX, gbase2 | 6);
            ak[4] = __shfl_sync(0xffffffffu, arX, gbase2 | 1);
            ak[5] = __shfl_sync(0xffffffffu, arX, gbase2 | 5);
            ak[6] = __shfl_sync(0xffffffffu, arX, gbase2 | 3);
            ak[7] = __shfl_sync(0xffffffffu, arX, gbase2 | 7);
            #pragma unroll
            for (int k = 0; k < 8; k++) {
                u64 ap = pk2(ak[k], ak[k]);
                fma2(P[k][0], ap, X0.x); fma2(P[k][1], ap, X0.y);
                fma2(P[k][2], ap, X1.x); fma2(P[k][3], ap, X1.y);
            }
        }
        {
            float ak[8];
            ak[0] = __shfl_sync(0xffffffffu, arY, gbase2 | 0);
            ak[1] = __shfl_sync(0xffffffffu, arY, gbase2 | 4);
            ak[2] = __shfl_sync(0xffffffffu, arY, gbase2 | 2);
            ak[3] = __shfl_sync(0xffffffffu, arY, gbase2 | 6);
            ak[4] = __shfl_sync(0xffffffffu, arY, gbase2 | 1);
            ak[5] = __shfl_sync(0xffffffffu, arY, gbase2 | 5);
            ak[6] = __shfl_sync(0xffffffffu, arY, gbase2 | 3);
            ak[7] = __shfl_sync(0xffffffffu, arY, gbase2 | 7);
            #pragma unroll
            for (int k = 0; k < 8; k++) {
                u64 ap = pk2(ak[k], ak[k]);
                fma2(P[k][0], ap, Y0.x); fma2(P[k][1], ap, Y0.y);
                fma2(P[k][2], ap, Y1.x); fma2(P[k][3], ap, Y1.y);
            }
        }
    }

    CP_WAIT0();
    __syncthreads();
    float* sP = sBuf;
    #pragma unroll
    for (int k = 0; k < 8; k++) {
        float x, y;
        float* dst = sP + warp * 2048 + k * 256;
        upk2(P[k][0], x, y); dst[4 * lane] = x;       dst[4 * lane + 1] = y;
        upk2(P[k][1], x, y); dst[4 * lane + 2] = x;   dst[4 * lane + 3] = y;
        upk2(P[k][2], x, y); dst[128 + 4 * lane] = x; dst[128 + 4 * lane + 1] = y;
        upk2(P[k][3], x, y); dst[128 + 4 * lane + 2] = x; dst[128 + 4 * lane + 3] = y;
    }
    if (lane < 8) { sSA[warp][slane] = SAl; sSW[warp][slane] = SWl; }
    __syncthreads();
    for (int t = threadIdx.x; t < 2048; t += 128) {
        int k = t >> 8, d = t & 255;
        float v = (sP[0 * 2048 + k * 256 + d] + sP[1 * 2048 + k * 256 + d]) +
                  (sP[2 * 2048 + k * 256 + d] + sP[3 * 2048 + k * 256 + d]);
        atomicAdd(&g_P[(size_t)(r8 + k) * 256 + d], v);
    }
    if (threadIdx.x < 8) {
        int k = threadIdx.x;
        atomicAdd(&g_SA[r8 + k], (sSA[0][k] + sSA[1][k]) + (sSA[2][k] + sSA[3][k]));
    } else if (threadIdx.x < 16) {
        int k = threadIdx.x - 8;
        atomicAdd(&g_SW[r8 + k], (sSW[0][k] + sSW[1][k]) + (sSW[2][k] + sSW[3][k]));
    }
}

// =================== kSlotB: 64 blocks x 8 rows, packed-weight GEMV ===================
__global__ void __launch_bounds__(1024) kSlotB(const float* __restrict__ gg, const float* __restrict__ gb,
                                               const float* __restrict__ bv,
                                               const float* __restrict__ b_ih, const float* __restrict__ b_hh,
                                               const float* __restrict__ lnf_g, const float* __restrict__ lnf_b,
                                               const float* __restrict__ b1, const float* __restrict__ b2,
                                               const float* __restrict__ ls_g, const float* __restrict__ ls_b,
                                               int last, float* __restrict__ out_slots) {
    __shared__ float sA[8][256];
    __shared__ float sB[8][256];
    __shared__ float sSL[8][256];
    __shared__ float sF1[8][512];
    __shared__ float sRed[8192];
    int j = threadIdx.x & 255, q = threadIdx.x >> 8;
    int r0 = blockIdx.x * 8;
    int rA = r0 + 2 * q, rB = rA + 1;
    int lA = 2 * q, lB = 2 * q + 1;

    // stage 1: un & slots (each group fills rows lA, lB)
    float snA, snB;
    {
        float ggj = gg[j], gbj = gb[j];
        float SAa = g_SA[rA], SWa = g_SW[rA];
        float invA = 1.0f / (SAa + EPSA);
        sA[lA][j] = (ggj * (g_P[(size_t)rA * 256 + j] - SWa) + gbj * SAa) * invA;
        sSL[lA][j] = g_slots[(size_t)rA * 256 + j];
        snA = SAa * invA;
        float SAb = g_SA[rB], SWb = g_SW[rB];
        float invB = 1.0f / (SAb + EPSA);
        sA[lB][j] = (ggj * (g_P[(size_t)rB * 256 + j] - SWb) + gbj * SAb) * invB;
        sSL[lB][j] = g_slots[(size_t)rB * 256 + j];
        snB = SAb * invB;
    }
    __syncthreads();

    // stage 2: x = un @ WvT + snorm*bv
    {
        float acc[8] = {};
        gemvPQ8(g_WvP, 256, 16, 16 * q, &sA[0][0], 256, j, acc);
        float xA, xB;
        reduceWave8(acc, sRed, q, j, xA, xB);
        float bvj = bv[j];
        sB[lA][j] = fmaf(snA, bvj, xA);
        sB[lB][j] = fmaf(snB, bvj, xB);
    }
    __syncthreads();

    // stage 3a: input gates (8 rows, 3 gates fused)
    float irA, izA, inA, irB, izB, inB;
    {
        float pir[8] = {}, piz[8] = {}, pin[8] = {};
        const float4* pw = (const float4*)g_WihP + (size_t)(16 * q) * 768 + j;
        #pragma unroll 2
        for (int bq_ = 0; bq_ < 16; bq_++) {
            float4 wr = pw[(size_t)bq_ * 768];
            float4 wz = pw[(size_t)bq_ * 768 + 256];
            float4 wn = pw[(size_t)bq_ * 768 + 512];
            #pragma unroll
            for (int r = 0; r < 8; r++) {
                float4 x = *(const float4*)(&sB[r][64 * q + 4 * bq_]);
                pir[r] = fmaf(x.x, wr.x, fmaf(x.y, wr.y, fmaf(x.z, wr.z, fmaf(x.w, wr.w, pir[r]))));
                piz[r] = fmaf(x.x, wz.x, fmaf(x.y, wz.y, fmaf(x.z, wz.z, fmaf(x.w, wz.w, piz[r]))));
                pin[r] = fmaf(x.x, wn.x, fmaf(x.y, wn.y, fmaf(x.z, wn.z, fmaf(x.w, wn.w, pin[r]))));
            }
        }
        reduceWave8(pir, sRed, q, j, irA, irB);
        reduceWave8(piz, sRed, q, j, izA, izB);
        reduceWave8(pin, sRed, q, j, inA, inB);
    }
    // stage 3b: hidden gates
    float hrA, hzA, hnA, hrB, hzB, hnB;
    {
        float phr[8] = {}, phz[8] = {}, phn[8] = {};
        const float4* pw = (const float4*)g_WhhP + (size_t)(16 * q) * 768 + j;
        #pragma unroll 2
        for (int bq_ = 0; bq_ < 16; bq_++) {
            float4 wr = pw[(size_t)bq_ * 768];
            float4 wz = pw[(size_t)bq_ * 768 + 256];
            float4 wn = pw[(size_t)bq_ * 768 + 512];
            #pragma unroll
            for (int r = 0; r < 8; r++) {
                float4 x = *(const float4*)(&sSL[r][64 * q + 4 * bq_]);
                phr[r] = fmaf(x.x, wr.x, fmaf(x.y, wr.y, fmaf(x.z, wr.z, fmaf(x.w, wr.w, phr[r]))));
                phz[r] = fmaf(x.x, wz.x, fmaf(x.y, wz.y, fmaf(x.z, wz.z, fmaf(x.w, wz.w, phz[r]))));
                phn[r] = fmaf(x.x, wn.x, fmaf(x.y, wn.y, fmaf(x.z, wn.z, fmaf(x.w, wn.w, phn[r]))));
            }
        }
        reduceWave8(phr, sRed, q, j, hrA, hrB);
        reduceWave8(phz, sRed, q, j, hzA, hzB);
        reduceWave8(phn, sRed, q, j, hnA, hnB);
    }

    // stage 4: GRU combine + ln_ff for rows lA, lB
    float hRegA, hRegB;
    {
        float bir = b_ih[j], biz = b_ih[256 + j], bin = b_ih[512 + j];
        float bhr = b_hh[j], bhz = b_hh[256 + j], bhn = b_hh[512 + j];
        float lgj = lnf_g[j], lbj = lnf_b[j];
        float rrA = 1.0f / (1.0f + __expf(-(irA + bir + hrA + bhr)));
        float zzA = 1.0f / (1.0f + __expf(-(izA + biz + hzA + bhz)));
        float nnA = tanhf(inA + bin + rrA * (hnA + bhn));
        float hA = (1.0f - zzA) * nnA + zzA * sSL[lA][j];
        float rrB = 1.0f / (1.0f + __expf(-(irB + bir + hrB + bhr)));
        float zzB = 1.0f / (1.0f + __expf(-(izB + biz + hzB + bhz)));
        float nnB = tanhf(inB + bin + rrB * (hnB + bhn));
        float hB = (1.0f - zzB) * nnB + zzB * sSL[lB][j];
        hRegA = hA; hRegB = hB;
        float aA = hA, bA = hA * hA;
        grpReduce2(aA, bA);
        float aB = hB, bB = hB * hB;
        grpReduce2(aB, bB);
        __syncthreads();   // sA (un) fully consumed before overwrite
        {
            float m = aA * (1.0f / 256.0f);
            float var = bA * (1.0f / 256.0f) - m * m;
            float rs = rsqrtf(var + EPSLN);
            sA[lA][j] = (hA - m) * rs * lgj + lbj;
        }
        {
            float m = aB * (1.0f / 256.0f);
            float var = bB * (1.0f / 256.0f) - m * m;
            float rs = rsqrtf(var + EPSLN);
            sA[lB][j] = (hB - m) * rs * lgj + lbj;
        }
    }
    __syncthreads();

    // stage 5: f1 = relu(ff @ W1T + b1), two 256-col halves, 8 rows
    {
        float f0[8] = {}, f1v[8] = {};
        const float4* p1 = (const float4*)g_W1P + (size_t)(16 * q) * 512 + j;
        #pragma unroll 2
        for (int bq_ = 0; bq_ < 16; bq_++) {
            float4 wa = p1[(size_t)bq_ * 512];
            float4 wb4 = p1[(size_t)bq_ * 512 + 256];
            #pragma unroll
            for (int r = 0; r < 8; r++) {
                float4 x = *(const float4*)(&sA[r][64 * q + 4 * bq_]);
                f0[r]  = fmaf(x.x, wa.x,  fmaf(x.y, wa.y,  fmaf(x.z, wa.z,  fmaf(x.w, wa.w,  f0[r]))));
                f1v[r] = fmaf(x.x, wb4.x, fmaf(x.y, wb4.y, fmaf(x.z, wb4.z, fmaf(x.w, wb4.w, f1v[r]))));
            }
        }
        float h0A, h0B, h1A, h1B;
        reduceWave8(f0, sRed, q, j, h0A, h0B);
        reduceWave8(f1v, sRed, q, j, h1A, h1B);
        float b1a = b1[j], b1b = b1[256 + j];
        sF1[lA][j]       = fmaxf(h0A + b1a, 0.f);
        sF1[lB][j]       = fmaxf(h0B + b1a, 0.f);
        sF1[lA][256 + j] = fmaxf(h1A + b1b, 0.f);
        sF1[lB][256 + j] = fmaxf(h1B + b1b, 0.f);
    }
    __syncthreads();

    // stage 6: new slots = h + f1 @ W2T + b2  (k=512, quarter = 128 = 32 blocks)
    float nsA, nsB;
    {
        float o[8] = {};
        gemvPQ8(g_W2P, 256, 32, 32 * q, &sF1[0][0], 512, j, o);
        float oA, oB;
        reduceWave8(o, sRed, q, j, oA, oB);
        float b2j = b2[j];
        nsA = hRegA + oA + b2j;
        nsB = hRegB + oB + b2j;
        g_slots[(size_t)rA * 256 + j] = nsA;
        g_slots[(size_t)rB * 256 + j] = nsB;
        if (last) {
            out_slots[(size_t)rA * 256 + j] = nsA;
            out_slots[(size_t)rB * 256 + j] = nsB;
        }
    }

    // fused next-iteration slotA
    if (!last) {
        float lsg = ls_g[j], lsb = ls_b[j];
        float aA = nsA, bA = nsA * nsA;
        grpReduce2(aA, bA);
        float aB = nsB, bB = nsB * nsB;
        grpReduce2(aB, bB);
        __syncthreads();   // sB fully consumed (stage 3a) before overwrite
        {
            float m = aA * (1.0f / 256.0f);
            float var = bA * (1.0f / 256.0f) - m * m;
            float rs = rsqrtf(var + EPSLN);
            sB[lA][j] = (nsA - m) * rs * lsg + lsb;
        }
        {
            float m = aB * (1.0f / 256.0f);
            float var = bB * (1.0f / 256.0f) - m * m;
            float rs = rsqrtf(var + EPSLN);
            sB[lB][j] = (nsB - m) * rs * lsg + lsb;
        }
        __syncthreads();
        slotABody8((const float (*)[256])sB, sRed, r0, q, j, gg, gb);
    }
}

// ---------------- launch ----------------
extern "C" void kernel_launch(void* const* d_in, const int* in_sizes, int n_in,
                              void* d_out, int out_size) {
    (void)in_sizes; (void)n_in; (void)out_size;
    const float* inputs  = (const float*)d_in[0];
    const float* noise   = (const float*)d_in[1];
    const float* slot_mu = (const float*)d_in[2];
    const float* slot_ls = (const float*)d_in[3];
    const float* Wq      = (const float*)d_in[4];
    const float* bq      = (const float*)d_in[5];
    const float* Wk      = (const float*)d_in[6];
    const float* bk      = (const float*)d_in[7];
    const float* Wv      = (const float*)d_in[8];
    const float* bv      = (const float*)d_in[9];
    const float* W_ih    = (const float*)d_in[10];
    const float* b_ih    = (const float*)d_in[11];
    const float* W_hh    = (const float*)d_in[12];
    const float* b_hh    = (const float*)d_in[13];
    const float* ln_in_g = (const float*)d_in[14];
    const float* ln_in_b = (const float*)d_in[15];
    const float* ln_s_g  = (const float*)d_in[16];
    const float* ln_s_b  = (const float*)d_in[17];
    const float* ln_ff_g = (const float*)d_in[18];
    const float* ln_ff_b = (const float*)d_in[19];
    const float* W1      = (const float*)d_in[20];
    const float* b1      = (const float*)d_in[21];
    const float* W2      = (const float*)d_in[22];
    const float* b2      = (const float*)d_in[23];

    float* out = (float*)d_out;
    float* out_slots = out;
    float* out_attn  = out + BK_ * D_;

    kSetup<<<1475, 256>>>(W_ih, W_hh, Wv, W1, W2, noise, slot_mu, slot_ls, Wq, Wk, bq, bk);
    kSlotA<<<64, 1024>>>(ln_s_g, ln_s_b, ln_in_g, ln_in_b);

    for (int it = 0; it < 3; it++) {
        int last = (it == 2);
        kFA<<<dim3(8, 64), 128>>>(inputs, last, out_attn);
        kSlotB<<<64, 1024>>>(ln_in_g, ln_in_b, bv, b_ih, b_hh,
                             ln_ff_g, ln_ff_b, b1, b2, ln_s_g, ln_s_b,
                             last, out_slots);
    }
}

// round 16
// speedup vs baseline: 1.0859x; 1.0859x over previous
#include <cuda_runtime.h>
#include <math.h>
#include <stdint.h>
#include <stddef.h>

// ---------------- problem dims ----------------
#define B_    64
#define N_    4096
#define DIN_  256
#define K_    8
#define D_    256
#define H_    512
#define BK_   512
#define SCALE_ 0.0625f
#define EPSLN 1e-5f
#define EPSA  1e-8f

typedef unsigned long long u64;

// ---------------- device scratch ----------------
__device__ __align__(16) float g_slots[BK_ * D_];
__device__ __align__(16) float g_gq[BK_ * D_];
__device__ float g_C1[BK_];
__device__ float g_C2[BK_];
__device__ __align__(16) float g_P[BK_ * D_];
__device__ float g_SA[BK_];
__device__ float g_SW[BK_];
__device__ float g_bqk[D_];
__device__ float g_wb[D_];
__device__ float g_c0;
// packed weights: Wp[(kb * Nout + o)*4 + t] = W[o][4*kb + t]
__device__ __align__(16) float g_WqkP[D_ * D_];
__device__ __align__(16) float g_WihP[3 * D_ * D_];
__device__ __align__(16) float g_WhhP[3 * D_ * D_];
__device__ __align__(16) float g_WvP[D_ * D_];
__device__ __align__(16) float g_W1P[H_ * D_];
__device__ __align__(16) float g_W2P[D_ * H_];

// ---------------- f32x2 packed helpers ----------------
__device__ __forceinline__ u64 pk2(float x, float y) {
    u64 r; asm("mov.b64 %0, {%1, %2};" : "=l"(r) : "f"(x), "f"(y)); return r;
}
__device__ __forceinline__ void upk2(u64 v, float& x, float& y) {
    asm("mov.b64 {%0, %1}, %2;" : "=f"(x), "=f"(y) : "l"(v));
}
__device__ __forceinline__ void fma2(u64& d, u64 a, u64 b) {
    asm("fma.rn.f32x2 %0, %1, %2, %0;" : "+l"(d) : "l"(a), "l"(b));
}
__device__ __forceinline__ u64 add2(u64 a, u64 b) {
    u64 r; asm("add.rn.f32x2 %0, %1, %2;" : "=l"(r) : "l"(a), "l"(b)); return r;
}
__device__ __forceinline__ u64 mul2(u64 a, u64 b) {
    u64 r; asm("mul.rn.f32x2 %0, %1, %2;" : "=l"(r) : "l"(a), "l"(b)); return r;
}

// ---------------- cp.async helpers ----------------
__device__ __forceinline__ void cpasync16(uint32_t saddr, const void* gptr) {
    asm volatile("cp.async.cg.shared.global [%0], [%1], 16;" :: "r"(saddr), "l"(gptr) : "memory");
}
#define CP_COMMIT() asm volatile("cp.async.commit_group;" ::: "memory")
#define CP_WAIT1()  asm volatile("cp.async.wait_group 1;" ::: "memory")
#define CP_WAIT0()  asm volatile("cp.async.wait_group 0;" ::: "memory")

// ---------------- block reduce (256-thread kernels) ----------------
__device__ __forceinline__ void blockReduce2(float& a, float& b) {
    #pragma unroll
    for (int o = 16; o; o >>= 1) {
        a += __shfl_xor_sync(0xffffffffu, a, o);
        b += __shfl_xor_sync(0xffffffffu, b, o);
    }
    __shared__ float sa[8], sb[8];
    __syncthreads();
    int w = threadIdx.x >> 5;
    if ((threadIdx.x & 31) == 0) { sa[w] = a; sb[w] = b; }
    __syncthreads();
    a = sa[threadIdx.x & 7];
    b = sb[threadIdx.x & 7];
    #pragma unroll
    for (int o = 4; o; o >>= 1) {
        a += __shfl_xor_sync(0xffffffffu, a, o);
        b += __shfl_xor_sync(0xffffffffu, b, o);
    }
}

// ---------------- group reduce: 1024 threads, 4 groups of 256 ----------------
__device__ __forceinline__ void grpReduce2(float& a, float& b) {
    #pragma unroll
    for (int o = 16; o; o >>= 1) {
        a += __shfl_xor_sync(0xffffffffu, a, o);
        b += __shfl_xor_sync(0xffffffffu, b, o);
    }
    __shared__ float sa[32], sb[32];
    int w = threadIdx.x >> 5;
    __syncthreads();
    if ((threadIdx.x & 31) == 0) { sa[w] = a; sb[w] = b; }
    __syncthreads();
    int g8 = (threadIdx.x >> 8) << 3;
    float ra = 0.f, rb = 0.f;
    #pragma unroll
    for (int i = 0; i < 8; i++) { ra += sa[g8 + i]; rb += sb[g8 + i]; }
    a = ra; b = rb;
}

// ---------------- packed GEMV (4 rows) ----------------
__device__ __forceinline__ void gemvPQ(const float* __restrict__ Wp, int Nout, int nblk, int kb0,
                                       const float* s_in, int in_stride, int j, float acc[4]) {
    const float4* p = (const float4*)Wp + (size_t)kb0 * Nout + j;
    #pragma unroll 4
    for (int b = 0; b < nblk; b++) {
        float4 w = p[(size_t)b * Nout];
        #pragma unroll
        for (int r = 0; r < 4; r++) {
            float4 x = *(const float4*)(s_in + r * in_stride + (kb0 + b) * 4);
            acc[r] = fmaf(x.x, w.x, fmaf(x.y, w.y, fmaf(x.z, w.z, fmaf(x.w, w.w, acc[r]))));
        }
    }
}

// ---------------- reduction waves ----------------
__device__ __forceinline__ float reduceWave(const float part[4], float* sRed, int q, int j) {
    __syncthreads();
    #pragma unroll
    for (int r = 0; r < 4; r++) sRed[((q << 2) + r) * 256 + j] = part[r];
    __syncthreads();
    return (sRed[(0 + q) * 256 + j] + sRed[(4 + q) * 256 + j]) +
           (sRed[(8 + q) * 256 + j] + sRed[(12 + q) * 256 + j]);
}

// 2 planes in one barrier pair
__device__ __forceinline__ void reduceWaveD(const float pa[4], const float pb[4],
                                            float* sRed, int q, int j, float& va, float& vb) {
    __syncthreads();
    #pragma unroll
    for (int r = 0; r < 4; r++) {
        sRed[((q << 2) + r) * 256 + j] = pa[r];
        sRed[4096 + ((q << 2) + r) * 256 + j] = pb[r];
    }
    __syncthreads();
    va = (sRed[(0 + q) * 256 + j] + sRed[(4 + q) * 256 + j]) +
         (sRed[(8 + q) * 256 + j] + sRed[(12 + q) * 256 + j]);
    vb = (sRed[4096 + (0 + q) * 256 + j] + sRed[4096 + (4 + q) * 256 + j]) +
         (sRed[4096 + (8 + q) * 256 + j] + sRed[4096 + (12 + q) * 256 + j]);
}

// 3 planes in one barrier pair
__device__ __forceinline__ void reduceWaveT(const float pa[4], const float pb[4], const float pc[4],
                                            float* sRed, int q, int j,
                                            float& va, float& vb, float& vc) {
    __syncthreads();
    #pragma unroll
    for (int r = 0; r < 4; r++) {
        sRed[((q << 2) + r) * 256 + j] = pa[r];
        sRed[4096 + ((q << 2) + r) * 256 + j] = pb[r];
        sRed[8192 + ((q << 2) + r) * 256 + j] = pc[r];
    }
    __syncthreads();
    va = (sRed[(0 + q) * 256 + j] + sRed[(4 + q) * 256 + j]) +
         (sRed[(8 + q) * 256 + j] + sRed[(12 + q) * 256 + j]);
    vb = (sRed[4096 + (0 + q) * 256 + j] + sRed[4096 + (4 + q) * 256 + j]) +
         (sRed[4096 + (8 + q) * 256 + j] + sRed[4096 + (12 + q) * 256 + j]);
    vc = (sRed[8192 + (0 + q) * 256 + j] + sRed[8192 + (4 + q) * 256 + j]) +
         (sRed[8192 + (8 + q) * 256 + j] + sRed[8192 + (12 + q) * 256 + j]);
}

// ---------------- slot-A body ----------------
__device__ __forceinline__ void slotABody(const float (*s_sn)[256], float* sRed,
                                          int r0, int q, int j,
                                          const float* __restrict__ gg, const float* __restrict__ gb) {
    float acc[4] = {0.f, 0.f, 0.f, 0.f};
    gemvPQ(g_WqkP, 256, 16, 16 * q, &s_sn[0][0], 256, j, acc);
    float qt = reduceWave(acc, sRed, q, j) + g_bqk[j];
    int row = r0 + q;
    float gq = gg[j] * qt;
    g_gq[(size_t)row * 256 + j] = gq;
    float c1 = gq;
    float c2 = fmaf(qt, gb[j], s_sn[q][j] * g_wb[j]);
    grpReduce2(c1, c2);
    if (j == 0) { g_C1[row] = c1; g_C2[row] = c2 + g_c0; }
    g_P[(size_t)row * 256 + j] = 0.f;
    if (j == 0) { g_SA[row] = 0.f; g_SW[row] = 0.f; }
}

// =================== SETUP ===================
__device__ __forceinline__ void packTile(const float* __restrict__ src, float* __restrict__ dst,
                                         int Nout, int Kb, int blk) {
    int e = blk * 256 + threadIdx.x;
    int o = e / Kb, kb = e - o * Kb;
    float4 v = *(const float4*)(src + (size_t)o * Kb * 4 + (size_t)kb * 4);
    *(float4*)(dst + ((size_t)kb * Nout + o) * 4) = v;
}

__global__ void __launch_bounds__(256) kSetup(const float* __restrict__ W_ih, const float* __restrict__ W_hh,
                                              const float* __restrict__ Wv, const float* __restrict__ W1,
                                              const float* __restrict__ W2, const float* __restrict__ noise,
                                              const float* __restrict__ mu, const float* __restrict__ ls,
                                              const float* __restrict__ Wq, const float* __restrict__ Wk,
                                              const float* __restrict__ bq, const float* __restrict__ bk) {
    int t = blockIdx.x;
    int i = threadIdx.x;
    if (t < 192)       packTile(W_ih, g_WihP, 768, 64, t);
    else if (t < 384)  packTile(W_hh, g_WhhP, 768, 64, t - 192);
    else if (t < 448)  packTile(Wv,   g_WvP,  256, 64, t - 384);
    else if (t < 576)  packTile(W1,   g_W1P,  512, 64, t - 448);
    else if (t < 704)  packTile(W2,   g_W2P,  256, 128, t - 576);
    else if (t < 1216) {
        int idx = (t - 704) * 256 + i;
        int d = idx & 255;
        g_slots[idx] = mu[d] + __expf(ls[d]) * noise[idx];
    } else if (t < 1472) {
        int jj = t - 1216;
        float acc[8] = {0.f,0.f,0.f,0.f,0.f,0.f,0.f,0.f};
        #pragma unroll 4
        for (int d = 0; d < 256; d += 8) {
            #pragma unroll
            for (int u = 0; u < 8; u++)
                acc[u] = fmaf(Wq[(d + u) * 256 + jj], Wk[(d + u) * 256 + i], acc[u]);
        }
        float v = (((acc[0] + acc[1]) + (acc[2] + acc[3])) + ((acc[4] + acc[5]) + (acc[6] + acc[7]))) * SCALE_;
        g_WqkP[(((size_t)(jj >> 2)) * 256 + i) * 4 + (jj & 3)] = v;
    } else if (t == 1472) {
        float a = 0.f;
        #pragma unroll 8
        for (int d = 0; d < 256; d++) a = fmaf(bq[d], Wk[d * 256 + i], a);
        g_bqk[i] = a * SCALE_;
    } else if (t == 1473) {
        float a = 0.f;
        #pragma unroll 8
        for (int d = 0; d < 256; d++) a = fmaf(Wq[d * 256 + i], bk[d], a);
        g_wb[i] = a * SCALE_;
    } else {
        float a = bq[i] * bk[i], dm = 0.f;
        blockReduce2(a, dm);
        if (i == 0) g_c0 = a * SCALE_;
    }
}

// =================== kSlotA (iteration 0 only) ===================
__global__ void __launch_bounds__(1024) kSlotA(const float* __restrict__ ls_g, const float* __restrict__ ls_b,
                                               const float* __restrict__ gg, const float* __restrict__ gb) {
    __shared__ float sSN[4][256];
    __shared__ float sRed[4096];
    int j = threadIdx.x & 255, q = threadIdx.x >> 8;
    int r0 = blockIdx.x * 4;
    float v = g_slots[(size_t)(r0 + q) * 256 + j];
    float a = v, b = v * v;
    grpReduce2(a, b);
    float m = a * (1.0f / 256.0f);
    float var = b * (1.0f / 256.0f) - m * m;
    float rs = rsqrtf(var + EPSLN);
    sSN[q][j] = (v - m) * rs * ls_g[j] + ls_b[j];
    __syncthreads();
    slotABody(sSN, sRed, r0, q, j, gg, gb);
}

// ============ kFA: cp.async-pipelined 2-row interleaved attention pass (R14, unchanged) ============
__global__ void __launch_bounds__(128, 4) kFA(const float* __restrict__ inputs,
                                              int last, float* __restrict__ out_attn) {
    int b = blockIdx.y;
    int warp = threadIdx.x >> 5, lane = threadIdx.x & 31;
    int row0 = blockIdx.x * 512 + warp * 128;
    int r8 = b * 8;
    int slane = ((lane & 1) << 2) | (lane & 2) | ((lane >> 2) & 1);

    __shared__ __align__(16) float sGQ[8][256];
    __shared__ __align__(16) float sBuf[8192];
    __shared__ float sSA[4][8], sSW[4][8];

    {
        const float4* src = (const float4*)(g_gq + (size_t)r8 * 256);
        #pragma unroll
        for (int e = threadIdx.x; e < 512; e += 128)
            ((float4*)sGQ)[e] = src[e];
    }
    float C1s = g_C1[r8 + slane], C2s = g_C2[r8 + slane];
    __syncthreads();

    float* ring = sBuf + warp * 1536;
    uint32_t ringAddr = (uint32_t)__cvta_generic_to_shared(ring);
    const float* gbase = inputs + ((size_t)b * N_ + row0) * 256;

    u64 P[8][4];
    #pragma unroll
    for (int k = 0; k < 8; k++) { P[k][0] = 0; P[k][1] = 0; P[k][2] = 0; P[k][3] = 0; }
    float SAl = 0.f, SWl = 0.f;

    #pragma unroll
    for (int pr = 0; pr < 2; pr++) {
        const float* gsrc = gbase + (size_t)pr * 512;
        uint32_t sdst = ringAddr + pr * 2048;
        #pragma unroll
        for (int c = 0; c < 4; c++)
            cpasync16(sdst + (c * 32 + lane) * 16, gsrc + (c * 32 + lane) * 4);
        CP_COMMIT();
    }

    #pragma unroll 1
    for (int p = 0; p < 64; p++) {
        CP_WAIT1();
        __syncwarp();
        const float* xb = ring + (p % 3) * 512;
        ulonglong2 X0 = *(const ulonglong2*)(xb + 4 * lane);
        ulonglong2 X1 = *(const ulonglong2*)(xb + 128 + 4 * lane);
        ulonglong2 Y0 = *(const ulonglong2*)(xb + 256 + 4 * lane);
        ulonglong2 Y1 = *(const ulonglong2*)(xb + 256 + 128 + 4 * lane);

        if (p < 62) {
            const float* gsrc = gbase + (size_t)(p + 2) * 512;
            uint32_t sdst = ringAddr + ((p + 2) % 3) * 2048;
            #pragma unroll
            for (int c = 0; c < 4; c++)
                cpasync16(sdst + (c * 32 + lane) * 16, gsrc + (c * 32 + lane) * 4);
        }
        CP_COMMIT();

        float sX, ssX, sY, ssY;
        {
            u64 s2  = add2(add2(X0.x, X0.y), add2(X1.x, X1.y));
            u64 ss2 = mul2(X0.x, X0.x);
            fma2(ss2, X0.y, X0.y); fma2(ss2, X1.x, X1.x); fma2(ss2, X1.y, X1.y);
            float lo, hi;
            upk2(s2, lo, hi);  sX  = lo + hi;
            upk2(ss2, lo, hi); ssX = lo + hi;
        }
        {
            u64 s2  = add2(add2(Y0.x, Y0.y), add2(Y1.x, Y1.y));
            u64 ss2 = mul2(Y0.x, Y0.x);
            fma2(ss2, Y0.y, Y0.y); fma2(ss2, Y1.x, Y1.x); fma2(ss2, Y1.y, Y1.y);
            float lo, hi;
            upk2(s2, lo, hi);  sY  = lo + hi;
            upk2(ss2, lo, hi); ssY = lo + hi;
        }
        bool odd = lane & 1;
        {
            float sendX = odd ? sX : ssX;
            float sendY = odd ? sY : ssY;
            float rcvX = __shfl_xor_sync(0xffffffffu, sendX, 1);
            float rcvY = __shfl_xor_sync(0xffffffffu, sendY, 1);
            float vX = odd ? (ssX + rcvX) : (sX + rcvX);
            float vY = odd ? (ssY + rcvY) : (sY + rcvY);
            vX += __shfl_xor_sync(0xffffffffu, vX, 2);
            vY += __shfl_xor_sync(0xffffffffu, vY, 2);
            vX += __shfl_xor_sync(0xffffffffu, vX, 4);
            vY += __shfl_xor_sync(0xffffffffu, vY, 4);
            vX += __shfl_xor_sync(0xffffffffu, vX, 8);
            vY += __shfl_xor_sync(0xffffffffu, vY, 8);
            vX += __shfl_xor_sync(0xffffffffu, vX, 16);
            vY += __shfl_xor_sync(0xffffffffu, vY, 16);
            float oX = __shfl_xor_sync(0xffffffffu, vX, 1);
            float oY = __shfl_xor_sync(0xffffffffu, vY, 1);
            sX  = odd ? oX : vX;  ssX = odd ? vX : oX;
            sY  = odd ? oY : vY;  ssY = odd ? vY : oY;
        }
        float mX   = sX * (1.0f / 256.0f);
        float mY   = sY * (1.0f / 256.0f);
        float rsX  = rsqrtf(fmaf(ssX, 1.0f / 256.0f, -mX * mX) + EPSLN);
        float rsY  = rsqrtf(fmaf(ssY, 1.0f / 256.0f, -mY * mY) + EPSLN);
        float wX   = mX * rsX;
        float wY   = mY * rsY;

        float dtX[8], dtY[8];
        #pragma unroll
        for (int k = 0; k < 8; k++) {
            ulonglong2 qa = *(const ulonglong2*)(&sGQ[k][4 * lane]);
            ulonglong2 qb = *(const ulonglong2*)(&sGQ[k][128 + 4 * lane]);
            u64 dX = mul2(X0.x, qa.x);
            u64 dY = mul2(Y0.x, qa.x);
            fma2(dX, X0.y, qa.y); fma2(dY, Y0.y, qa.y);
            fma2(dX, X1.x, qb.x); fma2(dY, Y1.x, qb.x);
            fma2(dX, X1.y, qb.y); fma2(dY, Y1.y, qb.y);
            float lo, hi;
            upk2(dX, lo, hi); dtX[k] = lo + hi;
            upk2(dY, lo, hi); dtY[k] = lo + hi;
        }
        float vdX, vdY;
        {
            bool c0 = lane & 1;
            float x0 = c0 ? dtX[0] : dtX[4], y0 = c0 ? dtY[0] : dtY[4];
            float x1 = c0 ? dtX[1] : dtX[5], y1 = c0 ? dtY[1] : dtY[5];
            float x2 = c0 ? dtX[2] : dtX[6], y2 = c0 ? dtY[2] : dtY[6];
            float x3 = c0 ? dtX[3] : dtX[7], y3 = c0 ? dtY[3] : dtY[7];
            x0 = __shfl_xor_sync(0xffffffffu, x0, 1); y0 = __shfl_xor_sync(0xffffffffu, y0, 1);
            x1 = __shfl_xor_sync(0xffffffffu, x1, 1); y1 = __shfl_xor_sync(0xffffffffu, y1, 1);
            x2 = __shfl_xor_sync(0xffffffffu, x2, 1); y2 = __shfl_xor_sync(0xffffffffu, y2, 1);
            x3 = __shfl_xor_sync(0xffffffffu, x3, 1); y3 = __shfl_xor_sync(0xffffffffu, y3, 1);
            float uX0 = (c0 ? dtX[4] : dtX[0]) + x0, uY0 = (c0 ? dtY[4] : dtY[0]) + y0;
            float uX1 = (c0 ? dtX[5] : dtX[1]) + x1, uY1 = (c0 ? dtY[5] : dtY[1]) + y1;
            float uX2 = (c0 ? dtX[6] : dtX[2]) + x2, uY2 = (c0 ? dtY[6] : dtY[2]) + y2;
            float uX3 = (c0 ? dtX[7] : dtX[3]) + x3, uY3 = (c0 ? dtY[7] : dtY[3]) + y3;
            bool c1 = lane & 2;
            float aX0 = c1 ? uX0 : uX2, aY0 = c1 ? uY0 : uY2;
            float aX1 = c1 ? uX1 : uX3, aY1 = c1 ? uY1 : uY3;
            aX0 = __shfl_xor_sync(0xffffffffu, aX0, 2); aY0 = __shfl_xor_sync(0xffffffffu, aY0, 2);
            aX1 = __shfl_xor_sync(0xffffffffu, aX1, 2); aY1 = __shfl_xor_sync(0xffffffffu, aY1, 2);
            float wX0 = (c1 ? uX2 : uX0) + aX0, wY0 = (c1 ? uY2 : uY0) + aY0;
            float wX1 = (c1 ? uX3 : uX1) + aX1, wY1 = (c1 ? uY3 : uY1) + aY1;
            bool c2 = lane & 4;
            float bX = c2 ? wX0 : wX1, bY = c2 ? wY0 : wY1;
            bX = __shfl_xor_sync(0xffffffffu, bX, 4); bY = __shfl_xor_sync(0xffffffffu, bY, 4);
            vdX = (c2 ? wX1 : wX0) + bX;
            vdY = (c2 ? wY1 : wY0) + bY;
            vdX += __shfl_xor_sync(0xffffffffu, vdX, 8);
            vdY += __shfl_xor_sync(0xffffffffu, vdY, 8);
            vdX += __shfl_xor_sync(0xffffffffu, vdX, 16);
            vdY += __shfl_xor_sync(0xffffffffu, vdY, 16);
        }
        float lgX = fmaf(rsX, vdX, fmaf(-wX, C1s, C2s));
        float lgY = fmaf(rsY, vdY, fmaf(-wY, C1s, C2s));
        float mxX = lgX, mxY = lgY;
        mxX = fmaxf(mxX, __shfl_xor_sync(0xffffffffu, mxX, 1));
        mxY = fmaxf(mxY, __shfl_xor_sync(0xffffffffu, mxY, 1));
        mxX = fmaxf(mxX, __shfl_xor_sync(0xffffffffu, mxX, 2));
        mxY = fmaxf(mxY, __shfl_xor_sync(0xffffffffu, mxY, 2));
        mxX = fmaxf(mxX, __shfl_xor_sync(0xffffffffu, mxX, 4));
        mxY = fmaxf(mxY, __shfl_xor_sync(0xffffffffu, mxY, 4));
        float eX = __expf(lgX - mxX);
        float eY = __expf(lgY - mxY);
        float smXv = eX, smYv = eY;
        smXv += __shfl_xor_sync(0xffffffffu, smXv, 1);
        smYv += __shfl_xor_sync(0xffffffffu, smYv, 1);
        smXv += __shfl_xor_sync(0xffffffffu, smXv, 2);
        smYv += __shfl_xor_sync(0xffffffffu, smYv, 2);
        smXv += __shfl_xor_sync(0xffffffffu, smXv, 4);
        smYv += __shfl_xor_sync(0xffffffffu, smYv, 4);
        float aX = __fdividef(eX, smXv);
        float aY = __fdividef(eY, smYv);
        SAl += aX + aY;
        SWl = fmaf(aX, wX, fmaf(aY, wY, SWl));
        if (last && lane < 8) {
            size_t base = (size_t)(r8 + slane) * N_ + row0 + 2 * p;
            out_attn[base] = aX;
            out_attn[base + 1] = aY;
        }

        float arX = aX * rsX;
        float arY = aY * rsY;
        int gbase2 = lane & 24;
        {
            float ak[8];
            ak[0] = __shfl_sync(0xffffffffu, arX, gbase2 | 0);
            ak[1] = __shfl_sync(0xffffffffu, arX, gbase2 | 4);
            ak[2] = __shfl_sync(0xffffffffu, arX, gbase2 | 2);
            ak[3] = __shfl_sync(0xffffffffu, arX, gbase2 | 6);
            ak[4] = __shfl_sync(0xffffffffu, arX, gbase2 | 1);
            ak[5] = __shfl_sync(0xffffffffu, arX, gbase2 | 5);
            ak[6] = __shfl_sync(0xffffffffu, arX, gbase2 | 3);
            ak[7] = __shfl_sync(0xffffffffu, arX, gbase2 | 7);
            #pragma unroll
            for (int k = 0; k < 8; k++) {
                u64 ap = pk2(ak[k], ak[k]);
                fma2(P[k][0], ap, X0.x); fma2(P[k][1], ap, X0.y);
                fma2(P[k][2], ap, X1.x); fma2(P[k][3], ap, X1.y);
            }
        }
        {
            float ak[8];
            ak[0] = __shfl_sync(0xffffffffu, arY, gbase2 | 0);
            ak[1] = __shfl_sync(0xffffffffu, arY, gbase2 | 4);
            ak[2] = __shfl_sync(0xffffffffu, arY, gbase2 | 2);
            ak[3] = __shfl_sync(0xffffffffu, arY, gbase2 | 6);
            ak[4] = __shfl_sync(0xffffffffu, arY, gbase2 | 1);
            ak[5] = __shfl_sync(0xffffffffu, arY, gbase2 | 5);
            ak[6] = __shfl_sync(0xffffffffu, arY, gbase2 | 3);
            ak[7] = __shfl_sync(0xffffffffu, arY, gbase2 | 7);
            #pragma unroll
            for (int k = 0; k < 8; k++) {
                u64 ap = pk2(ak[k], ak[k]);
                fma2(P[k][0], ap, Y0.x); fma2(P[k][1], ap, Y0.y);
                fma2(P[k][2], ap, Y1.x); fma2(P[k][3], ap, Y1.y);
            }
        }
    }

    CP_WAIT0();
    __syncthreads();
    float* sP = sBuf;
    #pragma unroll
    for (int k = 0; k < 8; k++) {
        float x, y;
        float* dst = sP + warp * 2048 + k * 256;
        upk2(P[k][0], x, y); dst[4 * lane] = x;       dst[4 * lane + 1] = y;
        upk2(P[k][1], x, y); dst[4 * lane + 2] = x;   dst[4 * lane + 3] = y;
        upk2(P[k][2], x, y); dst[128 + 4 * lane] = x; dst[128 + 4 * lane + 1] = y;
        upk2(P[k][3], x, y); dst[128 + 4 * lane + 2] = x; dst[128 + 4 * lane + 3] = y;
    }
    if (lane < 8) { sSA[warp][slane] = SAl; sSW[warp][slane] = SWl; }
    __syncthreads();
    for (int t = threadIdx.x; t < 2048; t += 128) {
        int k = t >> 8, d = t & 255;
        float v = (sP[0 * 2048 + k * 256 + d] + sP[1 * 2048 + k * 256 + d]) +
                  (sP[2 * 2048 + k * 256 + d] + sP[3 * 2048 + k * 256 + d]);
        atomicAdd(&g_P[(size_t)(r8 + k) * 256 + d], v);
    }
    if (threadIdx.x < 8) {
        int k = threadIdx.x;
        atomicAdd(&g_SA[r8 + k], (sSA[0][k] + sSA[1][k]) + (sSA[2][k] + sSA[3][k]));
    } else if (threadIdx.x < 16) {
        int k = threadIdx.x - 8;
        atomicAdd(&g_SW[r8 + k], (sSW[0][k] + sSW[1][k]) + (sSW[2][k] + sSW[3][k]));
    }
}

// =================== kSlotB: 128 blocks x 4 rows, merged reduction waves ===================
__global__ void __launch_bounds__(1024) kSlotB(const float* __restrict__ gg, const float* __restrict__ gb,
                                               const float* __restrict__ bv,
                                               const float* __restrict__ b_ih, const float* __restrict__ b_hh,
                                               const float* __restrict__ lnf_g, const float* __restrict__ lnf_b,
                                               const float* __restrict__ b1, const float* __restrict__ b2,
                                               const float* __restrict__ ls_g, const float* __restrict__ ls_b,
                                               int last, float* __restrict__ out_slots) {
    __shared__ float sA[4][256];
    __shared__ float sB[4][256];
    __shared__ float sSL[4][256];
    __shared__ float sF1[4][512];
    __shared__ float sRed[12288];   // 48KB: 3 reduction planes
    int j = threadIdx.x & 255, q = threadIdx.x >> 8;
    int r0 = blockIdx.x * 4;
    int row = r0 + q;

    float snorm;
    {
        float SA = g_SA[row], SW = g_SW[row];
        float inv = 1.0f / (SA + EPSA);
        float Pv = g_P[(size_t)row * 256 + j];
        sA[q][j] = (gg[j] * (Pv - SW) + gb[j] * SA) * inv;
        sSL[q][j] = g_slots[(size_t)row * 256 + j];
        snorm = SA * inv;
    }
    __syncthreads();

    // stage 2: x = un @ WvT + snorm*bv
    {
        float acc[4] = {0.f, 0.f, 0.f, 0.f};
        gemvPQ(g_WvP, 256, 16, 16 * q, &sA[0][0], 256, j, acc);
        float x = reduceWave(acc, sRed, q, j);
        sB[q][j] = fmaf(snorm, bv[j], x);
    }
    __syncthreads();

    // stage 3a: input gates — ONE merged reduction wave for all 3 gates
    float ir, iz, inn;
    {
        float pir[4] = {}, piz[4] = {}, pin[4] = {};
        const float4* pw = (const float4*)g_WihP + (size_t)(16 * q) * 768 + j;
        #pragma unroll 2
        for (int bq_ = 0; bq_ < 16; bq_++) {
            float4 wr = pw[(size_t)bq_ * 768];
            float4 wz = pw[(size_t)bq_ * 768 + 256];
            float4 wn = pw[(size_t)bq_ * 768 + 512];
            #pragma unroll
            for (int r = 0; r < 4; r++) {
                float4 x = *(const float4*)(&sB[r][64 * q + 4 * bq_]);
                pir[r] = fmaf(x.x, wr.x, fmaf(x.y, wr.y, fmaf(x.z, wr.z, fmaf(x.w, wr.w, pir[r]))));
                piz[r] = fmaf(x.x, wz.x, fmaf(x.y, wz.y, fmaf(x.z, wz.z, fmaf(x.w, wz.w, piz[r]))));
                pin[r] = fmaf(x.x, wn.x, fmaf(x.y, wn.y, fmaf(x.z, wn.z, fmaf(x.w, wn.w, pin[r]))));
            }
        }
        reduceWaveT(pir, piz, pin, sRed, q, j, ir, iz, inn);
    }
    // stage 3b: hidden gates — ONE merged wave
    float hr, hz, hn;
    {
        float phr[4] = {}, phz[4] = {}, phn[4] = {};
        const float4* pw = (const float4*)g_WhhP + (size_t)(16 * q) * 768 + j;
        #pragma unroll 2
        for (int bq_ = 0; bq_ < 16; bq_++) {
            float4 wr = pw[(size_t)bq_ * 768];
            float4 wz = pw[(size_t)bq_ * 768 + 256];
            float4 wn = pw[(size_t)bq_ * 768 + 512];
            #pragma unroll
            for (int r = 0; r < 4; r++) {
                float4 x = *(const float4*)(&sSL[r][64 * q + 4 * bq_]);
                phr[r] = fmaf(x.x, wr.x, fmaf(x.y, wr.y, fmaf(x.z, wr.z, fmaf(x.w, wr.w, phr[r]))));
                phz[r] = fmaf(x.x, wz.x, fmaf(x.y, wz.y, fmaf(x.z, wz.z, fmaf(x.w, wz.w, phz[r]))));
                phn[r] = fmaf(x.x, wn.x, fmaf(x.y, wn.y, fmaf(x.z, wn.z, fmaf(x.w, wn.w, phn[r]))));
            }
        }
        reduceWaveT(phr, phz, phn, sRed, q, j, hr, hz, hn);
    }

    // stage 4: GRU combine + ln_ff
    float h_reg;
    {
        float rr = 1.0f / (1.0f + __expf(-(ir + b_ih[j] + hr + b_hh[j])));
        float zz = 1.0f / (1.0f + __expf(-(iz + b_ih[256 + j] + hz + b_hh[256 + j])));
        float nn = tanhf(inn + b_ih[512 + j] + rr * (hn + b_hh[512 + j]));
        float h = (1.0f - zz) * nn + zz * sSL[q][j];
        h_reg = h;
        float a = h, bb = h * h;
        grpReduce2(a, bb);
        float m = a * (1.0f / 256.0f);
        float var = bb * (1.0f / 256.0f) - m * m;
        float rs = rsqrtf(var + EPSLN);
        __syncthreads();
        sA[q][j] = (h - m) * rs * lnf_g[j] + lnf_b[j];
    }
    __syncthreads();

    // stage 5: f1 = relu(ff @ W1T + b1) — both halves, ONE merged wave
    {
        float f0[4] = {}, f1v[4] = {};
        const float4* p1 = (const float4*)g_W1P + (size_t)(16 * q) * 512 + j;
        #pragma unroll 2
        for (int bq_ = 0; bq_ < 16; bq_++) {
            float4 wa = p1[(size_t)bq_ * 512];
            float4 wb4 = p1[(size_t)bq_ * 512 + 256];
            #pragma unroll
            for (int r = 0; r < 4; r++) {
                float4 x = *(const float4*)(&sA[r][64 * q + 4 * bq_]);
                f0[r]  = fmaf(x.x, wa.x,  fmaf(x.y, wa.y,  fmaf(x.z, wa.z,  fmaf(x.w, wa.w,  f0[r]))));
                f1v[r] = fmaf(x.x, wb4.x, fmaf(x.y, wb4.y, fmaf(x.z, wb4.z, fmaf(x.w, wb4.w, f1v[r]))));
            }
        }
        float h0, h1;
        reduceWaveD(f0, f1v, sRed, q, j, h0, h1);
        sF1[q][j]       = fmaxf(h0 + b1[j], 0.f);
        sF1[q][256 + j] = fmaxf(h1 + b1[256 + j], 0.f);
    }
    __syncthreads();

    // stage 6: new slots = h + f1 @ W2T + b2
    float ns;
    {
        float o[4] = {0.f, 0.f, 0.f, 0.f};
        gemvPQ(g_W2P, 256, 32, 32 * q, &sF1[0][0], 512, j, o);
        float oo = reduceWave(o, sRed, q, j);
        ns = h_reg + oo + b2[j];
        g_slots[(size_t)row * 256 + j] = ns;
        if (last) out_slots[(size_t)row * 256 + j] = ns;
    }

    // fused next-iteration slotA
    if (!last) {
        float a = ns, bb = ns * ns;
        grpReduce2(a, bb);
        float m = a * (1.0f / 256.0f);
        float var = bb * (1.0f / 256.0f) - m * m;
        float rs = rsqrtf(var + EPSLN);
        __syncthreads();
        sB[q][j] = (ns - m) * rs * ls_g[j] + ls_b[j];
        __syncthreads();
        slotABody((const float (*)[256])sB, sRed, r0, q, j, gg, gb);
    }
}

// ---------------- launch ----------------
extern "C" void kernel_launch(void* const* d_in, const int* in_sizes, int n_in,
                              void* d_out, int out_size) {
    (void)in_sizes; (void)n_in; (void)out_size;
    const float* inputs  = (const float*)d_in[0];
    const float* noise   = (const float*)d_in[1];
    const float* slot_mu = (const float*)d_in[2];
    const float* slot_ls = (const float*)d_in[3];
    const float* Wq      = (const float*)d_in[4];
    const float* bq      = (const float*)d_in[5];
    const float* Wk      = (const float*)d_in[6];
    const float* bk      = (const float*)d_in[7];
    const float* Wv      = (const float*)d_in[8];
    const float* bv      = (const float*)d_in[9];
    const float* W_ih    = (const float*)d_in[10];
    const float* b_ih    = (const float*)d_in[11];
    const float* W_hh    = (const float*)d_in[12];
    const float* b_hh    = (const float*)d_in[13];
    const float* ln_in_g = (const float*)d_in[14];
    const float* ln_in_b = (const float*)d_in[15];
    const float* ln_s_g  = (const float*)d_in[16];
    const float* ln_s_b  = (const float*)d_in[17];
    const float* ln_ff_g = (const float*)d_in[18];
    const float* ln_ff_b = (const float*)d_in[19];
    const float* W1      = (const float*)d_in[20];
    const float* b1      = (const float*)d_in[21];
    const float* W2      = (const float*)d_in[22];
    const float* b2      = (const float*)d_in[23];

    float* out = (float*)d_out;
    float* out_slots = out;
    float* out_attn  = out + BK_ * D_;

    kSetup<<<1475, 256>>>(W_ih, W_hh, Wv, W1, W2, noise, slot_mu, slot_ls, Wq, Wk, bq, bk);
    kSlotA<<<128, 1024>>>(ln_s_g, ln_s_b, ln_in_g, ln_in_b);

    for (int it = 0; it < 3; it++) {
        int last = (it == 2);
        kFA<<<dim3(8, 64), 128>>>(inputs, last, out_attn);
        kSlotB<<<128, 1024>>>(ln_in_g, ln_in_b, bv, b_ih, b_hh,
                              ln_ff_g, ln_ff_b, b1, b2, ln_s_g, ln_s_b,
                              last, out_slots);
    }
}